// round 3
// baseline (speedup 1.0000x reference)
#include <cuda_runtime.h>

#define BATCH 4
#define SEQ   2048
#define DIM   1024
#define NH    16
#define DH    64

// Scratch for projected Q/K/V in [B, H, N, Dh] layout (fp32).
__device__ float g_Q[BATCH * NH * SEQ * DH];
__device__ float g_K[BATCH * NH * SEQ * DH];
__device__ float g_V[BATCH * NH * SEQ * DH];

// ---------------------------------------------------------------------------
// Kernel 1: fused QKV projection.
//   out[b,h,n,d] = sum_k x[b,n,k] * W[k, h*64+d] + bias[h*64+d]
// blockIdx.z in {0,1,2} selects (Wq,bq,g_Q), (Wk,bk,g_K), (Wv,bv,g_V).
// Tile: 64(M) x 64(N) x 64(K); 256 threads (16x16), 4x4 micro-tile per thread.
// Thread col mapping col = c*16+tx makes the float4 reads of the transposed
// W tile (stride 68) phase-conflict-free.
// ---------------------------------------------------------------------------
__global__ __launch_bounds__(256) void qkv_kernel(
    const float* __restrict__ x,
    const float* __restrict__ Wq, const float* __restrict__ bq,
    const float* __restrict__ Wk, const float* __restrict__ bk,
    const float* __restrict__ Wv, const float* __restrict__ bv)
{
    __shared__ float Xs[64 * 64];    // [row][k], stride 64 (reads are broadcast)
    __shared__ float Wt[64 * 68];    // transposed: [n][k], stride 68 (pad)

    const float* W;
    const float* bias;
    float* out;
    int z = blockIdx.z;
    if (z == 0)      { W = Wq; bias = bq; out = g_Q; }
    else if (z == 1) { W = Wk; bias = bk; out = g_K; }
    else             { W = Wv; bias = bv; out = g_V; }

    const int m0 = blockIdx.y * 64;       // global row (b*SEQ + n)
    const int n0 = blockIdx.x * 64;       // global col (h*64 + d)
    const int tid = threadIdx.x;
    const int tx = tid & 15;
    const int ty = tid >> 4;

    float acc[4][4] = {};

    for (int k0 = 0; k0 < DIM; k0 += 64) {
        // Load X tile (64x64) with float4, no conflicts.
        for (int t = tid; t < 64 * 16; t += 256) {
            int r  = t >> 4;
            int c4 = (t & 15) << 2;
            *(float4*)&Xs[r * 64 + c4] =
                *(const float4*)&x[(size_t)(m0 + r) * DIM + k0 + c4];
        }
        // Load W tile transposed (coalesced global reads).
        for (int t = tid; t < 64 * 64; t += 256) {
            int k = t >> 6;
            int n = t & 63;
            Wt[n * 68 + k] = W[(size_t)(k0 + k) * DIM + n0 + n];
        }
        __syncthreads();

        #pragma unroll
        for (int kk = 0; kk < 64; kk += 4) {
            float4 xv[4], wv[4];
            #pragma unroll
            for (int r = 0; r < 4; r++)
                xv[r] = *(float4*)&Xs[(ty * 4 + r) * 64 + kk];
            #pragma unroll
            for (int c = 0; c < 4; c++)
                wv[c] = *(float4*)&Wt[(c * 16 + tx) * 68 + kk];
            #pragma unroll
            for (int r = 0; r < 4; r++)
                #pragma unroll
                for (int c = 0; c < 4; c++) {
                    acc[r][c] += xv[r].x * wv[c].x;
                    acc[r][c] += xv[r].y * wv[c].y;
                    acc[r][c] += xv[r].z * wv[c].z;
                    acc[r][c] += xv[r].w * wv[c].w;
                }
        }
        __syncthreads();
    }

    // Write to [B,H,N,Dh] scratch with bias.
    #pragma unroll
    for (int r = 0; r < 4; r++) {
        int m = m0 + ty * 4 + r;
        int b = m / SEQ;
        int n = m % SEQ;
        #pragma unroll
        for (int c = 0; c < 4; c++) {
            int col = n0 + c * 16 + tx;
            int h = col >> 6;
            int d = col & 63;
            out[(((size_t)(b * NH + h) * SEQ) + n) * DH + d] = acc[r][c] + bias[col];
        }
    }
}

// ---------------------------------------------------------------------------
// Kernel 2: flash attention, Br = Bc = 64, online softmax, fp32.
// One block per (b, h, 64-query tile). 256 threads (16x16), 4x4 micro-tiles.
// K-tile smem buffer is reused for the P tile (barrier-separated).
// Q is pre-scaled by 1/sqrt(Dh) at load.
// ---------------------------------------------------------------------------
__global__ __launch_bounds__(256, 2) void attn_kernel(float* __restrict__ out)
{
    extern __shared__ float sm[];
    float* Qs  = sm;                  // 64 x 64   (stride 64)
    float* KPs = sm + 64 * 64;        // 64 x 68   K tile, reused as P tile
    float* Vt  = KPs + 64 * 68;       // 64 x 68   V transposed: [d][kv]

    const int b  = blockIdx.z;
    const int h  = blockIdx.y;
    const int n0 = blockIdx.x * 64;
    const int tid = threadIdx.x;
    const int tx = tid & 15;
    const int ty = tid >> 4;

    const float* Qg = g_Q + ((size_t)(b * NH + h) * SEQ + n0) * DH;
    const float* Kg = g_K + (size_t)(b * NH + h) * SEQ * DH;
    const float* Vg = g_V + (size_t)(b * NH + h) * SEQ * DH;

    const float scale = 0.125f;   // 1/sqrt(64)

    // Load Q tile, pre-scaled.
    for (int t = tid; t < 64 * 16; t += 256) {
        int r  = t >> 4;
        int c4 = (t & 15) << 2;
        float4 v = *(const float4*)&Qg[(size_t)r * DH + c4];
        v.x *= scale; v.y *= scale; v.z *= scale; v.w *= scale;
        *(float4*)&Qs[r * 64 + c4] = v;
    }

    float o[4][4] = {};
    float mrow[4], lrow[4];
    #pragma unroll
    for (int r = 0; r < 4; r++) { mrow[r] = -1e30f; lrow[r] = 0.0f; }

    for (int j = 0; j < SEQ; j += 64) {
        __syncthreads();   // previous iter done reading KPs / Vt (also covers Qs load, iter 0)

        // Load K tile [kv][d] (float4, conflict-free phases).
        for (int t = tid; t < 64 * 16; t += 256) {
            int r  = t >> 4;
            int c4 = (t & 15) << 2;
            *(float4*)&KPs[r * 68 + c4] = *(const float4*)&Kg[(size_t)(j + r) * DH + c4];
        }
        // Load V tile transposed: Vt[d][kv].
        for (int t = tid; t < 64 * 64; t += 256) {
            int r = t >> 6;       // kv row
            int d = t & 63;       // head dim
            Vt[d * 68 + r] = Vg[(size_t)(j + r) * DH + d];
        }
        __syncthreads();

        // S = (Q*scale) @ K^T for this tile; thread owns rows ty*4+r, cols c*16+tx.
        float s[4][4] = {};
        #pragma unroll
        for (int kk = 0; kk < 64; kk += 4) {
            float4 qv[4], kv4[4];
            #pragma unroll
            for (int r = 0; r < 4; r++)
                qv[r] = *(float4*)&Qs[(ty * 4 + r) * 64 + kk];
            #pragma unroll
            for (int c = 0; c < 4; c++)
                kv4[c] = *(float4*)&KPs[(c * 16 + tx) * 68 + kk];
            #pragma unroll
            for (int r = 0; r < 4; r++)
                #pragma unroll
                for (int c = 0; c < 4; c++) {
                    s[r][c] += qv[r].x * kv4[c].x;
                    s[r][c] += qv[r].y * kv4[c].y;
                    s[r][c] += qv[r].z * kv4[c].z;
                    s[r][c] += qv[r].w * kv4[c].w;
                }
        }

        // Online softmax update; row reductions across tx via shfl (lane bits 0-3).
        #pragma unroll
        for (int r = 0; r < 4; r++) {
            float mx = s[r][0];
            #pragma unroll
            for (int c = 1; c < 4; c++) mx = fmaxf(mx, s[r][c]);
            mx = fmaxf(mx, __shfl_xor_sync(0xffffffffu, mx, 1));
            mx = fmaxf(mx, __shfl_xor_sync(0xffffffffu, mx, 2));
            mx = fmaxf(mx, __shfl_xor_sync(0xffffffffu, mx, 4));
            mx = fmaxf(mx, __shfl_xor_sync(0xffffffffu, mx, 8));
            float mnew = fmaxf(mrow[r], mx);
            float corr = __expf(mrow[r] - mnew);
            mrow[r] = mnew;
            float sum = 0.0f;
            #pragma unroll
            for (int c = 0; c < 4; c++) {
                float p = __expf(s[r][c] - mnew);
                s[r][c] = p;
                sum += p;
            }
            sum += __shfl_xor_sync(0xffffffffu, sum, 1);
            sum += __shfl_xor_sync(0xffffffffu, sum, 2);
            sum += __shfl_xor_sync(0xffffffffu, sum, 4);
            sum += __shfl_xor_sync(0xffffffffu, sum, 8);
            lrow[r] = lrow[r] * corr + sum;
            #pragma unroll
            for (int c = 0; c < 4; c++) o[r][c] *= corr;
        }

        __syncthreads();   // everyone done reading K before P overwrites the buffer
        #pragma unroll
        for (int r = 0; r < 4; r++)
            #pragma unroll
            for (int c = 0; c < 4; c++)
                KPs[(ty * 4 + r) * 68 + (c * 16 + tx)] = s[r][c];
        __syncthreads();

        // O += P @ V ; thread owns rows ty*4+r, dh-cols c*16+tx.
        #pragma unroll
        for (int kk = 0; kk < 64; kk += 4) {
            float4 pv[4], vv[4];
            #pragma unroll
            for (int r = 0; r < 4; r++)
                pv[r] = *(float4*)&KPs[(ty * 4 + r) * 68 + kk];
            #pragma unroll
            for (int c = 0; c < 4; c++)
                vv[c] = *(float4*)&Vt[(c * 16 + tx) * 68 + kk];
            #pragma unroll
            for (int r = 0; r < 4; r++)
                #pragma unroll
                for (int c = 0; c < 4; c++) {
                    o[r][c] += pv[r].x * vv[c].x;
                    o[r][c] += pv[r].y * vv[c].y;
                    o[r][c] += pv[r].z * vv[c].z;
                    o[r][c] += pv[r].w * vv[c].w;
                }
        }
    }

    // Normalize and write out[b, n, h*64+d].
    #pragma unroll
    for (int r = 0; r < 4; r++) {
        float inv = 1.0f / lrow[r];
        int n = n0 + ty * 4 + r;
        #pragma unroll
        for (int c = 0; c < 4; c++) {
            int d = c * 16 + tx;
            out[((size_t)(b * SEQ + n)) * DIM + h * DH + d] = o[r][c] * inv;
        }
    }
}

// ---------------------------------------------------------------------------
extern "C" void kernel_launch(void* const* d_in, const int* in_sizes, int n_in,
                              void* d_out, int out_size)
{
    (void)in_sizes; (void)n_in; (void)out_size;
    const float* x  = (const float*)d_in[0];
    const float* Wq = (const float*)d_in[1];
    const float* bq = (const float*)d_in[2];
    const float* Wk = (const float*)d_in[3];
    const float* bk = (const float*)d_in[4];
    const float* Wv = (const float*)d_in[5];
    const float* bv = (const float*)d_in[6];
    float* out = (float*)d_out;

    const int attn_smem = (64 * 64 + 2 * 64 * 68) * (int)sizeof(float);  // 51200 B
    cudaFuncSetAttribute(attn_kernel, cudaFuncAttributeMaxDynamicSharedMemorySize, attn_smem);

    qkv_kernel<<<dim3(DIM / 64, (BATCH * SEQ) / 64, 3), 256>>>(x, Wq, bq, Wk, bk, Wv, bv);
    attn_kernel<<<dim3(SEQ / 64, NH, BATCH), 256, attn_smem>>>(out);
}

// round 11
// speedup vs baseline: 1.3237x; 1.3237x over previous
#include <cuda_runtime.h>
#include <cuda_bf16.h>
#include <cstdint>

#define BATCH 4
#define SEQ   2048
#define DIM   1024
#define NH    16
#define DH    64

// ---------------------------------------------------------------------------
// Device scratch
// ---------------------------------------------------------------------------
__device__ float g_Q[BATCH * NH * SEQ * DH];
__device__ float g_K[BATCH * NH * SEQ * DH];
__device__ float g_V[BATCH * NH * SEQ * DH];

// bf16 split operands
__device__ __nv_bfloat16 g_Xh[BATCH * SEQ * DIM];
__device__ __nv_bfloat16 g_Xl[BATCH * SEQ * DIM];
__device__ __nv_bfloat16 g_Wh[3][DIM * DIM];   // transposed: [n][k]
__device__ __nv_bfloat16 g_Wl[3][DIM * DIM];

// ---------------------------------------------------------------------------
// mma.sync helpers (sm_80+ features, valid on the sm_103 ptxas target)
// ---------------------------------------------------------------------------
__device__ __forceinline__ uint32_t smem_to_u32(const void* p) {
    uint32_t a;
    asm("{ .reg .u64 t; cvta.to.shared.u64 t, %1; cvt.u32.u64 %0, t; }" : "=r"(a) : "l"(p));
    return a;
}
__device__ __forceinline__ void ldmatrix_x4(uint32_t& r0, uint32_t& r1,
                                            uint32_t& r2, uint32_t& r3, uint32_t addr) {
    asm volatile("ldmatrix.sync.aligned.m8n8.x4.shared.b16 {%0,%1,%2,%3}, [%4];"
                 : "=r"(r0), "=r"(r1), "=r"(r2), "=r"(r3) : "r"(addr));
}
__device__ __forceinline__ void mma_bf16(float* d, const uint32_t* a, uint32_t b0, uint32_t b1) {
    asm volatile("mma.sync.aligned.m16n8k16.row.col.f32.bf16.bf16.f32 "
                 "{%0,%1,%2,%3}, {%4,%5,%6,%7}, {%8,%9}, {%0,%1,%2,%3};"
                 : "+f"(d[0]), "+f"(d[1]), "+f"(d[2]), "+f"(d[3])
                 : "r"(a[0]), "r"(a[1]), "r"(a[2]), "r"(a[3]), "r"(b0), "r"(b1));
}

// ---------------------------------------------------------------------------
// Conversion kernels: fp32 -> bf16 hi/lo split
// ---------------------------------------------------------------------------
__global__ __launch_bounds__(256) void cvt_x_kernel(const float* __restrict__ x)
{
    int i = (blockIdx.x * 256 + threadIdx.x) * 4;
    float4 v = *(const float4*)&x[i];
    __nv_bfloat16 h0 = __float2bfloat16_rn(v.x), h1 = __float2bfloat16_rn(v.y);
    __nv_bfloat16 h2 = __float2bfloat16_rn(v.z), h3 = __float2bfloat16_rn(v.w);
    g_Xh[i]   = h0; g_Xh[i+1] = h1; g_Xh[i+2] = h2; g_Xh[i+3] = h3;
    g_Xl[i]   = __float2bfloat16_rn(v.x - __bfloat162float(h0));
    g_Xl[i+1] = __float2bfloat16_rn(v.y - __bfloat162float(h1));
    g_Xl[i+2] = __float2bfloat16_rn(v.z - __bfloat162float(h2));
    g_Xl[i+3] = __float2bfloat16_rn(v.w - __bfloat162float(h3));
}

// Transpose + split: W[k][n] (fp32) -> Wh[n][k], Wl[n][k] (bf16)
__global__ __launch_bounds__(256) void cvt_w_kernel(
    const float* __restrict__ Wq, const float* __restrict__ Wk, const float* __restrict__ Wv)
{
    __shared__ float t[32][33];
    int z = blockIdx.z;
    const float* W = (z == 0) ? Wq : (z == 1) ? Wk : Wv;
    int tx = threadIdx.x, ty = threadIdx.y;      // block (32, 8)
    int n0 = blockIdx.x * 32, k0 = blockIdx.y * 32;
    #pragma unroll
    for (int j = 0; j < 4; j++)
        t[ty + j * 8][tx] = W[(size_t)(k0 + ty + j * 8) * DIM + n0 + tx];
    __syncthreads();
    #pragma unroll
    for (int j = 0; j < 4; j++) {
        float v = t[tx][ty + j * 8];             // = W[k0+tx][n0+ty+j*8]
        int n = n0 + ty + j * 8, k = k0 + tx;
        __nv_bfloat16 h = __float2bfloat16_rn(v);
        g_Wh[z][(size_t)n * DIM + k] = h;
        g_Wl[z][(size_t)n * DIM + k] = __float2bfloat16_rn(v - __bfloat162float(h));
    }
}

// ---------------------------------------------------------------------------
// QKV GEMM via mma.sync bf16 (HMMA). BM=128, BN=128, BK=32, 96 k-stages
// (3 split terms x 32 chunks). 8 warps: 4(m) x 2(n), each warp 32x64.
// Smem rows padded to 40 bf16 (80 B) -> conflict-free ldmatrix phases.
// ---------------------------------------------------------------------------
#define SA 40   // smem row stride in bf16 (80 bytes)

__global__ __launch_bounds__(256, 2) void qkv_mma_kernel(
    const float* __restrict__ bq, const float* __restrict__ bk, const float* __restrict__ bv)
{
    __shared__ __align__(16) __nv_bfloat16 smA[2][128 * SA];
    __shared__ __align__(16) __nv_bfloat16 smB[2][128 * SA];

    const int tid  = threadIdx.x;
    const int lane = tid & 31;
    const int wid  = tid >> 5;
    const int warp_m = wid & 3;         // 0..3  -> 32-row group
    const int warp_n = wid >> 2;        // 0..1  -> 64-col group

    const int z  = blockIdx.z;
    const int m0 = blockIdx.y * 128;    // global row (b*SEQ+n)
    const int n0 = blockIdx.x * 128;    // global col (h*64+d)

    const __nv_bfloat16* Wh = g_Wh[z];
    const __nv_bfloat16* Wl = g_Wl[z];
    const float* bias = (z == 0) ? bq : (z == 1) ? bk : bv;
    float* out = (z == 0) ? g_Q : (z == 1) ? g_K : g_V;

    float acc[2][8][4];
    #pragma unroll
    for (int mt = 0; mt < 2; mt++)
        #pragma unroll
        for (int j = 0; j < 8; j++)
            #pragma unroll
            for (int c = 0; c < 4; c++) acc[mt][j][c] = 0.0f;

    // per-thread global-load slots: t = tid + i*256; r = t>>2 (row), c = t&3 (16B chunk)
    const int lr = tid >> 2;
    const int lc = tid & 3;

    auto srcA = [&](int s) -> const __nv_bfloat16* {
        int term = s >> 5;
        int kc = (s & 31) << 5;
        return ((term == 2) ? g_Xl : g_Xh) + (size_t)m0 * DIM + kc;
    };
    auto srcB = [&](int s) -> const __nv_bfloat16* {
        int term = s >> 5;
        int kc = (s & 31) << 5;
        return ((term == 1) ? Wl : Wh) + (size_t)n0 * DIM + kc;
    };

    uint4 pa0, pa1, pb0, pb1;
    {   // stage 0 -> buffer 0
        const __nv_bfloat16* As = srcA(0);
        const __nv_bfloat16* Bs = srcB(0);
        pa0 = *(const uint4*)(As + (size_t)lr * DIM + lc * 8);
        pa1 = *(const uint4*)(As + (size_t)(lr + 64) * DIM + lc * 8);
        pb0 = *(const uint4*)(Bs + (size_t)lr * DIM + lc * 8);
        pb1 = *(const uint4*)(Bs + (size_t)(lr + 64) * DIM + lc * 8);
        *(uint4*)&smA[0][lr * SA + lc * 8]        = pa0;
        *(uint4*)&smA[0][(lr + 64) * SA + lc * 8] = pa1;
        *(uint4*)&smB[0][lr * SA + lc * 8]        = pb0;
        *(uint4*)&smB[0][(lr + 64) * SA + lc * 8] = pb1;
    }
    __syncthreads();

    const uint32_t smA_u32 = smem_to_u32(&smA[0][0]);
    const uint32_t smB_u32 = smem_to_u32(&smB[0][0]);
    const uint32_t bufA_bytes = 128 * SA * 2;
    const uint32_t bufB_bytes = 128 * SA * 2;

    for (int s = 0; s < 96; s++) {
        const int b = s & 1;
        // issue next-stage global loads early
        if (s + 1 < 96) {
            const __nv_bfloat16* As = srcA(s + 1);
            const __nv_bfloat16* Bs = srcB(s + 1);
            pa0 = *(const uint4*)(As + (size_t)lr * DIM + lc * 8);
            pa1 = *(const uint4*)(As + (size_t)(lr + 64) * DIM + lc * 8);
            pb0 = *(const uint4*)(Bs + (size_t)lr * DIM + lc * 8);
            pb1 = *(const uint4*)(Bs + (size_t)(lr + 64) * DIM + lc * 8);
        }

        // compute on buffer b: two k16 halves
        const uint32_t aBase = smA_u32 + b * bufA_bytes;
        const uint32_t bBase = smB_u32 + b * bufB_bytes;
        #pragma unroll
        for (int kk = 0; kk < 2; kk++) {
            uint32_t afr[2][4];
            #pragma unroll
            for (int mt = 0; mt < 2; mt++) {
                uint32_t addr = aBase
                    + (uint32_t)(warp_m * 32 + mt * 16 + (lane & 15)) * (SA * 2)
                    + kk * 32 + (lane >> 4) * 16;
                ldmatrix_x4(afr[mt][0], afr[mt][1], afr[mt][2], afr[mt][3], addr);
            }
            #pragma unroll
            for (int nt = 0; nt < 4; nt++) {
                uint32_t b0, b1, b2, b3;
                uint32_t addr = bBase
                    + (uint32_t)(warp_n * 64 + nt * 16 + (lane & 7) + ((lane >> 4) & 1) * 8) * (SA * 2)
                    + kk * 32 + ((lane >> 3) & 1) * 16;
                ldmatrix_x4(b0, b1, b2, b3, addr);
                #pragma unroll
                for (int mt = 0; mt < 2; mt++) {
                    mma_bf16(acc[mt][nt * 2],     afr[mt], b0, b1);
                    mma_bf16(acc[mt][nt * 2 + 1], afr[mt], b2, b3);
                }
            }
        }

        // store next stage into the other buffer
        if (s + 1 < 96) {
            const int nb = 1 - b;
            *(uint4*)&smA[nb][lr * SA + lc * 8]        = pa0;
            *(uint4*)&smA[nb][(lr + 64) * SA + lc * 8] = pa1;
            *(uint4*)&smB[nb][lr * SA + lc * 8]        = pb0;
            *(uint4*)&smB[nb][(lr + 64) * SA + lc * 8] = pb1;
        }
        __syncthreads();
    }

    // Epilogue: D rows (groupID, groupID+8), cols (2*ti, 2*ti+1) per mma tile.
    const int g  = lane >> 2;
    const int ti = lane & 3;
    #pragma unroll
    for (int mt = 0; mt < 2; mt++) {
        #pragma unroll
        for (int j = 0; j < 8; j++) {
            int col = n0 + warp_n * 64 + j * 8 + ti * 2;
            int h = col >> 6, d = col & 63;
            float bx = bias[col], by = bias[col + 1];
            #pragma unroll
            for (int rr = 0; rr < 2; rr++) {
                int m = m0 + warp_m * 32 + mt * 16 + g + rr * 8;
                int bb = m >> 11, n = m & 2047;
                float2 v;
                v.x = acc[mt][j][rr * 2 + 0] + bx;
                v.y = acc[mt][j][rr * 2 + 1] + by;
                *(float2*)&out[(((size_t)(bb * NH + h) * SEQ) + n) * DH + d] = v;
            }
        }
    }
}

// ---------------------------------------------------------------------------
// Flash attention (unchanged — known good, 1.98 ms)
// ---------------------------------------------------------------------------
__global__ __launch_bounds__(256, 2) void attn_kernel(float* __restrict__ out)
{
    extern __shared__ float sm[];
    float* Qs  = sm;                  // 64 x 64
    float* KPs = sm + 64 * 64;        // 64 x 68   K tile, reused as P tile
    float* Vt  = KPs + 64 * 68;       // 64 x 68   V transposed

    const int b  = blockIdx.z;
    const int h  = blockIdx.y;
    const int n0 = blockIdx.x * 64;
    const int tid = threadIdx.x;
    const int tx = tid & 15;
    const int ty = tid >> 4;

    const float* Qg = g_Q + ((size_t)(b * NH + h) * SEQ + n0) * DH;
    const float* Kg = g_K + (size_t)(b * NH + h) * SEQ * DH;
    const float* Vg = g_V + (size_t)(b * NH + h) * SEQ * DH;

    const float scale = 0.125f;

    for (int t = tid; t < 64 * 16; t += 256) {
        int r  = t >> 4;
        int c4 = (t & 15) << 2;
        float4 v = *(const float4*)&Qg[(size_t)r * DH + c4];
        v.x *= scale; v.y *= scale; v.z *= scale; v.w *= scale;
        *(float4*)&Qs[r * 64 + c4] = v;
    }

    float o[4][4] = {};
    float mrow[4], lrow[4];
    #pragma unroll
    for (int r = 0; r < 4; r++) { mrow[r] = -1e30f; lrow[r] = 0.0f; }

    for (int j = 0; j < SEQ; j += 64) {
        __syncthreads();
        for (int t = tid; t < 64 * 16; t += 256) {
            int r  = t >> 4;
            int c4 = (t & 15) << 2;
            *(float4*)&KPs[r * 68 + c4] = *(const float4*)&Kg[(size_t)(j + r) * DH + c4];
        }
        for (int t = tid; t < 64 * 64; t += 256) {
            int r = t >> 6;
            int d = t & 63;
            Vt[d * 68 + r] = Vg[(size_t)(j + r) * DH + d];
        }
        __syncthreads();

        float s[4][4] = {};
        #pragma unroll
        for (int kk = 0; kk < 64; kk += 4) {
            float4 qv[4], kv4[4];
            #pragma unroll
            for (int r = 0; r < 4; r++) qv[r] = *(float4*)&Qs[(ty * 4 + r) * 64 + kk];
            #pragma unroll
            for (int c = 0; c < 4; c++) kv4[c] = *(float4*)&KPs[(c * 16 + tx) * 68 + kk];
            #pragma unroll
            for (int r = 0; r < 4; r++)
                #pragma unroll
                for (int c = 0; c < 4; c++) {
                    s[r][c] += qv[r].x * kv4[c].x;
                    s[r][c] += qv[r].y * kv4[c].y;
                    s[r][c] += qv[r].z * kv4[c].z;
                    s[r][c] += qv[r].w * kv4[c].w;
                }
        }

        #pragma unroll
        for (int r = 0; r < 4; r++) {
            float mx = s[r][0];
            #pragma unroll
            for (int c = 1; c < 4; c++) mx = fmaxf(mx, s[r][c]);
            mx = fmaxf(mx, __shfl_xor_sync(0xffffffffu, mx, 1));
            mx = fmaxf(mx, __shfl_xor_sync(0xffffffffu, mx, 2));
            mx = fmaxf(mx, __shfl_xor_sync(0xffffffffu, mx, 4));
            mx = fmaxf(mx, __shfl_xor_sync(0xffffffffu, mx, 8));
            float mnew = fmaxf(mrow[r], mx);
            float corr = __expf(mrow[r] - mnew);
            mrow[r] = mnew;
            float sum = 0.0f;
            #pragma unroll
            for (int c = 0; c < 4; c++) {
                float p = __expf(s[r][c] - mnew);
                s[r][c] = p;
                sum += p;
            }
            sum += __shfl_xor_sync(0xffffffffu, sum, 1);
            sum += __shfl_xor_sync(0xffffffffu, sum, 2);
            sum += __shfl_xor_sync(0xffffffffu, sum, 4);
            sum += __shfl_xor_sync(0xffffffffu, sum, 8);
            lrow[r] = lrow[r] * corr + sum;
            #pragma unroll
            for (int c = 0; c < 4; c++) o[r][c] *= corr;
        }

        __syncthreads();
        #pragma unroll
        for (int r = 0; r < 4; r++)
            #pragma unroll
            for (int c = 0; c < 4; c++)
                KPs[(ty * 4 + r) * 68 + (c * 16 + tx)] = s[r][c];
        __syncthreads();

        #pragma unroll
        for (int kk = 0; kk < 64; kk += 4) {
            float4 pv[4], vv[4];
            #pragma unroll
            for (int r = 0; r < 4; r++) pv[r] = *(float4*)&KPs[(ty * 4 + r) * 68 + kk];
            #pragma unroll
            for (int c = 0; c < 4; c++) vv[c] = *(float4*)&Vt[(c * 16 + tx) * 68 + kk];
            #pragma unroll
            for (int r = 0; r < 4; r++)
                #pragma unroll
                for (int c = 0; c < 4; c++) {
                    o[r][c] += pv[r].x * vv[c].x;
                    o[r][c] += pv[r].y * vv[c].y;
                    o[r][c] += pv[r].z * vv[c].z;
                    o[r][c] += pv[r].w * vv[c].w;
                }
        }
    }

    #pragma unroll
    for (int r = 0; r < 4; r++) {
        float inv = 1.0f / lrow[r];
        int n = n0 + ty * 4 + r;
        #pragma unroll
        for (int c = 0; c < 4; c++) {
            int d = c * 16 + tx;
            out[((size_t)(b * SEQ + n)) * DIM + h * DH + d] = o[r][c] * inv;
        }
    }
}

// ---------------------------------------------------------------------------
extern "C" void kernel_launch(void* const* d_in, const int* in_sizes, int n_in,
                              void* d_out, int out_size)
{
    (void)in_sizes; (void)n_in; (void)out_size;
    const float* x  = (const float*)d_in[0];
    const float* Wq = (const float*)d_in[1];
    const float* bq = (const float*)d_in[2];
    const float* Wk = (const float*)d_in[3];
    const float* bk = (const float*)d_in[4];
    const float* Wv = (const float*)d_in[5];
    const float* bv = (const float*)d_in[6];
    float* out = (float*)d_out;

    const int attn_smem = (64 * 64 + 2 * 64 * 68) * (int)sizeof(float);
    cudaFuncSetAttribute(attn_kernel, cudaFuncAttributeMaxDynamicSharedMemorySize, attn_smem);

    cvt_x_kernel<<<(BATCH * SEQ * DIM) / (256 * 4), 256>>>(x);
    cvt_w_kernel<<<dim3(DIM / 32, DIM / 32, 3), dim3(32, 8)>>>(Wq, Wk, Wv);
    qkv_mma_kernel<<<dim3(DIM / 128, (BATCH * SEQ) / 128, 3), 256>>>(bq, bk, bv);
    attn_kernel<<<dim3(SEQ / 64, NH, BATCH), 256, attn_smem>>>(out);
}

// round 15
// speedup vs baseline: 2.7309x; 2.0631x over previous
#include <cuda_runtime.h>
#include <cuda_bf16.h>
#include <cstdint>

#define BATCH 4
#define SEQ   2048
#define DIM   1024
#define NH    16
#define DH    64

// ---------------------------------------------------------------------------
// Device scratch: bf16 hi/lo splits
// ---------------------------------------------------------------------------
__device__ __nv_bfloat16 g_Qh[BATCH * NH * SEQ * DH];
__device__ __nv_bfloat16 g_Ql[BATCH * NH * SEQ * DH];
__device__ __nv_bfloat16 g_Kh[BATCH * NH * SEQ * DH];
__device__ __nv_bfloat16 g_Kl[BATCH * NH * SEQ * DH];
__device__ __nv_bfloat16 g_Vh[BATCH * NH * SEQ * DH];
__device__ __nv_bfloat16 g_Vl[BATCH * NH * SEQ * DH];

__device__ __nv_bfloat16 g_Xh[BATCH * SEQ * DIM];
__device__ __nv_bfloat16 g_Xl[BATCH * SEQ * DIM];
__device__ __nv_bfloat16 g_Wh[3][DIM * DIM];   // transposed: [n][k]
__device__ __nv_bfloat16 g_Wl[3][DIM * DIM];

// ---------------------------------------------------------------------------
// helpers (sm_80+ features, valid on the sm_103 ptxas target)
// ---------------------------------------------------------------------------
__device__ __forceinline__ uint32_t smem_to_u32(const void* p) {
    uint32_t a;
    asm("{ .reg .u64 t; cvta.to.shared.u64 t, %1; cvt.u32.u64 %0, t; }" : "=r"(a) : "l"(p));
    return a;
}
__device__ __forceinline__ void ldmatrix_x4(uint32_t& r0, uint32_t& r1,
                                            uint32_t& r2, uint32_t& r3, uint32_t addr) {
    asm volatile("ldmatrix.sync.aligned.m8n8.x4.shared.b16 {%0,%1,%2,%3}, [%4];"
                 : "=r"(r0), "=r"(r1), "=r"(r2), "=r"(r3) : "r"(addr));
}
__device__ __forceinline__ void ldmatrix_x4_trans(uint32_t& r0, uint32_t& r1,
                                                  uint32_t& r2, uint32_t& r3, uint32_t addr) {
    asm volatile("ldmatrix.sync.aligned.m8n8.x4.trans.shared.b16 {%0,%1,%2,%3}, [%4];"
                 : "=r"(r0), "=r"(r1), "=r"(r2), "=r"(r3) : "r"(addr));
}
__device__ __forceinline__ void mma_bf16(float* d, const uint32_t* a, uint32_t b0, uint32_t b1) {
    asm volatile("mma.sync.aligned.m16n8k16.row.col.f32.bf16.bf16.f32 "
                 "{%0,%1,%2,%3}, {%4,%5,%6,%7}, {%8,%9}, {%0,%1,%2,%3};"
                 : "+f"(d[0]), "+f"(d[1]), "+f"(d[2]), "+f"(d[3])
                 : "r"(a[0]), "r"(a[1]), "r"(a[2]), "r"(a[3]), "r"(b0), "r"(b1));
}
#define CP_ASYNC16(dst, src) \
    asm volatile("cp.async.cg.shared.global [%0], [%1], 16;" :: "r"(dst), "l"(src))
#define CP_COMMIT() asm volatile("cp.async.commit_group;")
#define CP_WAIT0()  asm volatile("cp.async.wait_group 0;")

__device__ __forceinline__ void split_pack(float a, float b, uint32_t& hi, uint32_t& lo) {
    __nv_bfloat16 ha = __float2bfloat16_rn(a), hb = __float2bfloat16_rn(b);
    __nv_bfloat16 la = __float2bfloat16_rn(a - __bfloat162float(ha));
    __nv_bfloat16 lb = __float2bfloat16_rn(b - __bfloat162float(hb));
    hi = (uint32_t)*(uint16_t*)&ha | ((uint32_t)*(uint16_t*)&hb << 16);
    lo = (uint32_t)*(uint16_t*)&la | ((uint32_t)*(uint16_t*)&lb << 16);
}

// ---------------------------------------------------------------------------
// Conversion kernels: fp32 -> bf16 hi/lo split (GEMM inputs)
// ---------------------------------------------------------------------------
__global__ __launch_bounds__(256) void cvt_x_kernel(const float* __restrict__ x)
{
    int i = (blockIdx.x * 256 + threadIdx.x) * 4;
    float4 v = *(const float4*)&x[i];
    __nv_bfloat16 h0 = __float2bfloat16_rn(v.x), h1 = __float2bfloat16_rn(v.y);
    __nv_bfloat16 h2 = __float2bfloat16_rn(v.z), h3 = __float2bfloat16_rn(v.w);
    g_Xh[i]   = h0; g_Xh[i+1] = h1; g_Xh[i+2] = h2; g_Xh[i+3] = h3;
    g_Xl[i]   = __float2bfloat16_rn(v.x - __bfloat162float(h0));
    g_Xl[i+1] = __float2bfloat16_rn(v.y - __bfloat162float(h1));
    g_Xl[i+2] = __float2bfloat16_rn(v.z - __bfloat162float(h2));
    g_Xl[i+3] = __float2bfloat16_rn(v.w - __bfloat162float(h3));
}

__global__ __launch_bounds__(256) void cvt_w_kernel(
    const float* __restrict__ Wq, const float* __restrict__ Wk, const float* __restrict__ Wv)
{
    __shared__ float t[32][33];
    int z = blockIdx.z;
    const float* W = (z == 0) ? Wq : (z == 1) ? Wk : Wv;
    int tx = threadIdx.x, ty = threadIdx.y;      // block (32, 8)
    int n0 = blockIdx.x * 32, k0 = blockIdx.y * 32;
    #pragma unroll
    for (int j = 0; j < 4; j++)
        t[ty + j * 8][tx] = W[(size_t)(k0 + ty + j * 8) * DIM + n0 + tx];
    __syncthreads();
    #pragma unroll
    for (int j = 0; j < 4; j++) {
        float v = t[tx][ty + j * 8];
        int n = n0 + ty + j * 8, k = k0 + tx;
        __nv_bfloat16 h = __float2bfloat16_rn(v);
        g_Wh[z][(size_t)n * DIM + k] = h;
        g_Wl[z][(size_t)n * DIM + k] = __float2bfloat16_rn(v - __bfloat162float(h));
    }
}

// ---------------------------------------------------------------------------
// QKV GEMM via mma.sync bf16. Epilogue writes bf16 hi/lo splits directly
// (Q pre-scaled by 1/sqrt(Dh)).
// ---------------------------------------------------------------------------
#define SA 40   // smem row stride in bf16 (80 bytes)

__global__ __launch_bounds__(256, 2) void qkv_mma_kernel(
    const float* __restrict__ bq, const float* __restrict__ bk, const float* __restrict__ bv)
{
    __shared__ __align__(16) __nv_bfloat16 smA[2][128 * SA];
    __shared__ __align__(16) __nv_bfloat16 smB[2][128 * SA];

    const int tid  = threadIdx.x;
    const int lane = tid & 31;
    const int wid  = tid >> 5;
    const int warp_m = wid & 3;
    const int warp_n = wid >> 2;

    const int z  = blockIdx.z;
    const int m0 = blockIdx.y * 128;
    const int n0 = blockIdx.x * 128;

    const __nv_bfloat16* Wh = g_Wh[z];
    const __nv_bfloat16* Wl = g_Wl[z];
    const float* bias = (z == 0) ? bq : (z == 1) ? bk : bv;
    __nv_bfloat16* outh = (z == 0) ? g_Qh : (z == 1) ? g_Kh : g_Vh;
    __nv_bfloat16* outl = (z == 0) ? g_Ql : (z == 1) ? g_Kl : g_Vl;
    const float osc = (z == 0) ? 0.125f : 1.0f;

    float acc[2][8][4];
    #pragma unroll
    for (int mt = 0; mt < 2; mt++)
        #pragma unroll
        for (int j = 0; j < 8; j++)
            #pragma unroll
            for (int c = 0; c < 4; c++) acc[mt][j][c] = 0.0f;

    const int lr = tid >> 2;
    const int lc = tid & 3;

    auto srcA = [&](int s) -> const __nv_bfloat16* {
        int term = s >> 5;
        int kc = (s & 31) << 5;
        return ((term == 2) ? g_Xl : g_Xh) + (size_t)m0 * DIM + kc;
    };
    auto srcB = [&](int s) -> const __nv_bfloat16* {
        int term = s >> 5;
        int kc = (s & 31) << 5;
        return ((term == 1) ? Wl : Wh) + (size_t)n0 * DIM + kc;
    };

    uint4 pa0, pa1, pb0, pb1;
    {
        const __nv_bfloat16* As = srcA(0);
        const __nv_bfloat16* Bs = srcB(0);
        pa0 = *(const uint4*)(As + (size_t)lr * DIM + lc * 8);
        pa1 = *(const uint4*)(As + (size_t)(lr + 64) * DIM + lc * 8);
        pb0 = *(const uint4*)(Bs + (size_t)lr * DIM + lc * 8);
        pb1 = *(const uint4*)(Bs + (size_t)(lr + 64) * DIM + lc * 8);
        *(uint4*)&smA[0][lr * SA + lc * 8]        = pa0;
        *(uint4*)&smA[0][(lr + 64) * SA + lc * 8] = pa1;
        *(uint4*)&smB[0][lr * SA + lc * 8]        = pb0;
        *(uint4*)&smB[0][(lr + 64) * SA + lc * 8] = pb1;
    }
    __syncthreads();

    const uint32_t smA_u32 = smem_to_u32(&smA[0][0]);
    const uint32_t smB_u32 = smem_to_u32(&smB[0][0]);
    const uint32_t buf_bytes = 128 * SA * 2;

    for (int s = 0; s < 96; s++) {
        const int b = s & 1;
        if (s + 1 < 96) {
            const __nv_bfloat16* As = srcA(s + 1);
            const __nv_bfloat16* Bs = srcB(s + 1);
            pa0 = *(const uint4*)(As + (size_t)lr * DIM + lc * 8);
            pa1 = *(const uint4*)(As + (size_t)(lr + 64) * DIM + lc * 8);
            pb0 = *(const uint4*)(Bs + (size_t)lr * DIM + lc * 8);
            pb1 = *(const uint4*)(Bs + (size_t)(lr + 64) * DIM + lc * 8);
        }

        const uint32_t aBase = smA_u32 + b * buf_bytes;
        const uint32_t bBase = smB_u32 + b * buf_bytes;
        #pragma unroll
        for (int kk = 0; kk < 2; kk++) {
            uint32_t afr[2][4];
            #pragma unroll
            for (int mt = 0; mt < 2; mt++) {
                uint32_t addr = aBase
                    + (uint32_t)(warp_m * 32 + mt * 16 + (lane & 15)) * (SA * 2)
                    + kk * 32 + (lane >> 4) * 16;
                ldmatrix_x4(afr[mt][0], afr[mt][1], afr[mt][2], afr[mt][3], addr);
            }
            #pragma unroll
            for (int nt = 0; nt < 4; nt++) {
                uint32_t b0, b1, b2, b3;
                uint32_t addr = bBase
                    + (uint32_t)(warp_n * 64 + nt * 16 + (lane & 7) + ((lane >> 4) & 1) * 8) * (SA * 2)
                    + kk * 32 + ((lane >> 3) & 1) * 16;
                ldmatrix_x4(b0, b1, b2, b3, addr);
                #pragma unroll
                for (int mt = 0; mt < 2; mt++) {
                    mma_bf16(acc[mt][nt * 2],     afr[mt], b0, b1);
                    mma_bf16(acc[mt][nt * 2 + 1], afr[mt], b2, b3);
                }
            }
        }

        if (s + 1 < 96) {
            const int nb = 1 - b;
            *(uint4*)&smA[nb][lr * SA + lc * 8]        = pa0;
            *(uint4*)&smA[nb][(lr + 64) * SA + lc * 8] = pa1;
            *(uint4*)&smB[nb][lr * SA + lc * 8]        = pb0;
            *(uint4*)&smB[nb][(lr + 64) * SA + lc * 8] = pb1;
        }
        __syncthreads();
    }

    // Epilogue: split + write hi/lo bf16 to [B,H,N,Dh]
    const int g  = lane >> 2;
    const int ti = lane & 3;
    #pragma unroll
    for (int mt = 0; mt < 2; mt++) {
        #pragma unroll
        for (int j = 0; j < 8; j++) {
            int col = n0 + warp_n * 64 + j * 8 + ti * 2;
            int h = col >> 6, d = col & 63;
            float bx = bias[col], by = bias[col + 1];
            #pragma unroll
            for (int rr = 0; rr < 2; rr++) {
                int m = m0 + warp_m * 32 + mt * 16 + g + rr * 8;
                int bb = m >> 11, n = m & 2047;
                float vx = (acc[mt][j][rr * 2 + 0] + bx) * osc;
                float vy = (acc[mt][j][rr * 2 + 1] + by) * osc;
                __nv_bfloat16 hx = __float2bfloat16_rn(vx), hy = __float2bfloat16_rn(vy);
                __nv_bfloat16 lx = __float2bfloat16_rn(vx - __bfloat162float(hx));
                __nv_bfloat16 ly = __float2bfloat16_rn(vy - __bfloat162float(hy));
                size_t idx = (((size_t)(bb * NH + h) * SEQ) + n) * DH + d;
                __nv_bfloat162 hv; hv.x = hx; hv.y = hy;
                __nv_bfloat162 lv; lv.x = lx; lv.y = ly;
                *(__nv_bfloat162*)&outh[idx] = hv;
                *(__nv_bfloat162*)&outl[idx] = lv;
            }
        }
    }
}

// ---------------------------------------------------------------------------
// Flash attention via mma.sync bf16. Br=128 (8 warps x 16 rows), Bc=64.
// S = Qh*Kh + Qh*Kl + Ql*Kh ; O += Ph*Vh + Ph*Vl + Pl*Vh (P split in regs).
// KV tiles double-buffered via cp.async; smem stride 72 bf16 (144B).
// ---------------------------------------------------------------------------
#define ST      72
#define ST_B    (ST * 2)            // 144 bytes
#define TILE_B  (64 * ST_B)         // 9216
#define STAGE_B (4 * TILE_B)        // 36864
#define ATTN_SMEM (2 * STAGE_B)     // 73728

__global__ __launch_bounds__(256) void attn_mma_kernel(float* __restrict__ out)
{
    extern __shared__ __align__(16) char smem[];
    const uint32_t smem_u = smem_to_u32(smem);
    const int tid = threadIdx.x, lane = tid & 31, wid = tid >> 5;
    const int b = blockIdx.z, h = blockIdx.y;
    const int n0 = blockIdx.x * 128;
    const int g = lane >> 2, ti = lane & 3;

    const size_t bh = (size_t)(b * NH + h) * SEQ;
    const __nv_bfloat16* Qhp = g_Qh + (bh + n0) * DH;
    const __nv_bfloat16* Qlp = g_Ql + (bh + n0) * DH;
    const __nv_bfloat16* kvsrc[4] = {
        g_Kh + bh * DH, g_Kl + bh * DH, g_Vh + bh * DH, g_Vl + bh * DH };

    // ---- stage Q tiles, extract A fragments (resident in regs) ----
    uint32_t qh[4][4], ql[4][4];
    {
        const int r = tid >> 3, c = tid & 7;          // 4 slots: rows r, r+32, r+64, r+96
        #pragma unroll
        for (int i = 0; i < 4; i++)
            *(uint4*)(smem + (r + i * 32) * ST_B + c * 16) =
                *(const uint4*)(Qhp + (size_t)(r + i * 32) * DH + c * 8);
        __syncthreads();
        #pragma unroll
        for (int kk = 0; kk < 4; kk++) {
            uint32_t addr = smem_u + (uint32_t)(wid * 16 + (lane & 15)) * ST_B
                          + kk * 32 + (lane >> 4) * 16;
            ldmatrix_x4(qh[kk][0], qh[kk][1], qh[kk][2], qh[kk][3], addr);
        }
        __syncthreads();
        #pragma unroll
        for (int i = 0; i < 4; i++)
            *(uint4*)(smem + (r + i * 32) * ST_B + c * 16) =
                *(const uint4*)(Qlp + (size_t)(r + i * 32) * DH + c * 8);
        __syncthreads();
        #pragma unroll
        for (int kk = 0; kk < 4; kk++) {
            uint32_t addr = smem_u + (uint32_t)(wid * 16 + (lane & 15)) * ST_B
                          + kk * 32 + (lane >> 4) * 16;
            ldmatrix_x4(ql[kk][0], ql[kk][1], ql[kk][2], ql[kk][3], addr);
        }
        __syncthreads();
    }

    // ---- prologue: stage-0 KV via cp.async ----
    {
        const int r = tid >> 3, c = tid & 7;   // idx slots: r in [0,32), +32
        #pragma unroll
        for (int t = 0; t < 4; t++)
            #pragma unroll
            for (int i = 0; i < 2; i++) {
                int row = r + i * 32;
                CP_ASYNC16(smem_u + t * TILE_B + row * ST_B + c * 16,
                           kvsrc[t] + (size_t)row * DH + c * 8);
            }
        CP_COMMIT();
        CP_WAIT0();
        __syncthreads();
    }

    float m0 = -1e30f, m1 = -1e30f, l0 = 0.0f, l1 = 0.0f;
    float oac[8][4];
    #pragma unroll
    for (int nt = 0; nt < 8; nt++)
        #pragma unroll
        for (int c = 0; c < 4; c++) oac[nt][c] = 0.0f;

    const int lrr = tid >> 3, lcc = tid & 7;

    for (int s = 0; s < 32; s++) {
        const uint32_t base = smem_u + (s & 1) * STAGE_B;

        // prefetch next KV stage into the other buffer (free since last sync)
        if (s + 1 < 32) {
            const uint32_t nb = smem_u + ((s + 1) & 1) * STAGE_B;
            const size_t jn = (size_t)(s + 1) * 64;
            #pragma unroll
            for (int t = 0; t < 4; t++)
                #pragma unroll
                for (int i = 0; i < 2; i++) {
                    int row = lrr + i * 32;
                    CP_ASYNC16(nb + t * TILE_B + row * ST_B + lcc * 16,
                               kvsrc[t] + (jn + row) * DH + lcc * 8);
                }
            CP_COMMIT();
        }

        // ---- S = Qh*Kh + Ql*Kh + Qh*Kl ----
        float sacc[8][4];
        #pragma unroll
        for (int nt = 0; nt < 8; nt++)
            #pragma unroll
            for (int c = 0; c < 4; c++) sacc[nt][c] = 0.0f;

        const uint32_t khB = base, klB = base + TILE_B;
        const uint32_t raK = (uint32_t)((lane & 7) + ((lane >> 4) & 1) * 8) * ST_B
                           + ((lane >> 3) & 1) * 16;
        #pragma unroll
        for (int kk = 0; kk < 4; kk++) {
            #pragma unroll
            for (int nt = 0; nt < 4; nt++) {
                uint32_t b0, b1, b2, b3;
                uint32_t ra = (uint32_t)(nt * 16) * ST_B + kk * 32 + raK;
                ldmatrix_x4(b0, b1, b2, b3, khB + ra);
                mma_bf16(sacc[nt * 2],     qh[kk], b0, b1);
                mma_bf16(sacc[nt * 2 + 1], qh[kk], b2, b3);
                mma_bf16(sacc[nt * 2],     ql[kk], b0, b1);
                mma_bf16(sacc[nt * 2 + 1], ql[kk], b2, b3);
                ldmatrix_x4(b0, b1, b2, b3, klB + ra);
                mma_bf16(sacc[nt * 2],     qh[kk], b0, b1);
                mma_bf16(sacc[nt * 2 + 1], qh[kk], b2, b3);
            }
        }

        // ---- online softmax (rows g and g+8 of this warp's m16) ----
        float mx0 = -1e30f, mx1 = -1e30f;
        #pragma unroll
        for (int nt = 0; nt < 8; nt++) {
            mx0 = fmaxf(mx0, fmaxf(sacc[nt][0], sacc[nt][1]));
            mx1 = fmaxf(mx1, fmaxf(sacc[nt][2], sacc[nt][3]));
        }
        mx0 = fmaxf(mx0, __shfl_xor_sync(0xffffffffu, mx0, 1));
        mx0 = fmaxf(mx0, __shfl_xor_sync(0xffffffffu, mx0, 2));
        mx1 = fmaxf(mx1, __shfl_xor_sync(0xffffffffu, mx1, 1));
        mx1 = fmaxf(mx1, __shfl_xor_sync(0xffffffffu, mx1, 2));
        float mn0 = fmaxf(m0, mx0), mn1 = fmaxf(m1, mx1);
        float c0 = __expf(m0 - mn0), c1 = __expf(m1 - mn1);
        m0 = mn0; m1 = mn1;
        float s0 = 0.0f, s1 = 0.0f;
        #pragma unroll
        for (int nt = 0; nt < 8; nt++) {
            float p0 = __expf(sacc[nt][0] - mn0);
            float p1 = __expf(sacc[nt][1] - mn0);
            float p2 = __expf(sacc[nt][2] - mn1);
            float p3 = __expf(sacc[nt][3] - mn1);
            sacc[nt][0] = p0; sacc[nt][1] = p1; sacc[nt][2] = p2; sacc[nt][3] = p3;
            s0 += p0 + p1; s1 += p2 + p3;
        }
        s0 += __shfl_xor_sync(0xffffffffu, s0, 1);
        s0 += __shfl_xor_sync(0xffffffffu, s0, 2);
        s1 += __shfl_xor_sync(0xffffffffu, s1, 1);
        s1 += __shfl_xor_sync(0xffffffffu, s1, 2);
        l0 = l0 * c0 + s0; l1 = l1 * c1 + s1;
        #pragma unroll
        for (int nt = 0; nt < 8; nt++) {
            oac[nt][0] *= c0; oac[nt][1] *= c0;
            oac[nt][2] *= c1; oac[nt][3] *= c1;
        }

        // ---- split P into hi/lo A fragments (register-only) ----
        uint32_t ph[4][4], pl[4][4];
        #pragma unroll
        for (int j = 0; j < 4; j++) {
            split_pack(sacc[2 * j][0],     sacc[2 * j][1],     ph[j][0], pl[j][0]);
            split_pack(sacc[2 * j][2],     sacc[2 * j][3],     ph[j][1], pl[j][1]);
            split_pack(sacc[2 * j + 1][0], sacc[2 * j + 1][1], ph[j][2], pl[j][2]);
            split_pack(sacc[2 * j + 1][2], sacc[2 * j + 1][3], ph[j][3], pl[j][3]);
        }

        // ---- O += Ph*Vh + Pl*Vh + Ph*Vl  (ldmatrix.trans on V) ----
        const uint32_t vhB = base + 2 * TILE_B, vlB = base + 3 * TILE_B;
        const uint32_t raV = (uint32_t)(lane & 15) * ST_B + ((lane >> 4) & 1) * 16;
        #pragma unroll
        for (int kk = 0; kk < 4; kk++) {
            #pragma unroll
            for (int nt = 0; nt < 4; nt++) {
                uint32_t b0, b1, b2, b3;
                uint32_t ra = (uint32_t)(kk * 16) * ST_B + nt * 32 + raV;
                ldmatrix_x4_trans(b0, b1, b2, b3, vhB + ra);
                mma_bf16(oac[nt * 2],     ph[kk], b0, b1);
                mma_bf16(oac[nt * 2 + 1], ph[kk], b2, b3);
                mma_bf16(oac[nt * 2],     pl[kk], b0, b1);
                mma_bf16(oac[nt * 2 + 1], pl[kk], b2, b3);
                ldmatrix_x4_trans(b0, b1, b2, b3, vlB + ra);
                mma_bf16(oac[nt * 2],     ph[kk], b0, b1);
                mma_bf16(oac[nt * 2 + 1], ph[kk], b2, b3);
            }
        }

        if (s + 1 < 32) CP_WAIT0();
        __syncthreads();
    }

    // ---- normalize + write out[b, n, h*64+d] ----
    const float inv0 = 1.0f / l0, inv1 = 1.0f / l1;
    const int row0 = n0 + wid * 16 + g;
    float* o0 = out + ((size_t)b * SEQ + row0) * DIM + h * DH;
    float* o1 = o0 + 8 * DIM;
    #pragma unroll
    for (int nt = 0; nt < 8; nt++) {
        float2 v0; v0.x = oac[nt][0] * inv0; v0.y = oac[nt][1] * inv0;
        float2 v1; v1.x = oac[nt][2] * inv1; v1.y = oac[nt][3] * inv1;
        *(float2*)&o0[nt * 8 + ti * 2] = v0;
        *(float2*)&o1[nt * 8 + ti * 2] = v1;
    }
}

// ---------------------------------------------------------------------------
extern "C" void kernel_launch(void* const* d_in, const int* in_sizes, int n_in,
                              void* d_out, int out_size)
{
    (void)in_sizes; (void)n_in; (void)out_size;
    const float* x  = (const float*)d_in[0];
    const float* Wq = (const float*)d_in[1];
    const float* bq = (const float*)d_in[2];
    const float* Wk = (const float*)d_in[3];
    const float* bk = (const float*)d_in[4];
    const float* Wv = (const float*)d_in[5];
    const float* bv = (const float*)d_in[6];
    float* out = (float*)d_out;

    cudaFuncSetAttribute(attn_mma_kernel, cudaFuncAttributeMaxDynamicSharedMemorySize, ATTN_SMEM);

    cvt_x_kernel<<<(BATCH * SEQ * DIM) / (256 * 4), 256>>>(x);
    cvt_w_kernel<<<dim3(DIM / 32, DIM / 32, 3), dim3(32, 8)>>>(Wq, Wk, Wv);
    qkv_mma_kernel<<<dim3(DIM / 128, (BATCH * SEQ) / 128, 3), 256>>>(bq, bk, bv);
    attn_mma_kernel<<<dim3(SEQ / 128, NH, BATCH), 256, ATTN_SMEM>>>(out);
}